// round 15
// baseline (speedup 1.0000x reference)
#include <cuda_runtime.h>
#include <cuda_fp16.h>
#include <stdint.h>
#include <math.h>

#define N_NODES 100000
#define N_EDGES 1600000
#define CCH 128
#define FULLM 0xffffffffu
#define SCAN_B 1024
#define SCAN_G ((N_NODES + SCAN_B - 1) / SCAN_B)   // 98
#define GEMM_BX ((N_NODES + 127) / 128)            // 782
#define FILL_B  ((N_EDGES + 255) / 256)            // 6250 (degree prep)
#define FILL_B5 ((N_EDGES + 511) / 512)            // 3125 (csr fill @512)
#define WPREP_B 128
#define MLPP_B  21

// ---------------- device scratch (zero-initialized at load; kernels self-clean) ----------------
__device__ uint4 g_feat_h[(size_t)N_NODES * 32];
__device__ uint4 g_atab[(size_t)N_NODES * 16];
__device__ int   g_deg [N_NODES];
__device__ float g_dinv[N_NODES];
__device__ int   g_off [N_NODES + 1];
__device__ int   g_cur [N_NODES];
__device__ int   g_csr [N_EDGES];
__device__ int   g_bsum[SCAN_G];
__device__ float g_csum[CCH];
__device__ float g_wtf[2 * CCH * CCH];
__device__ unsigned short g_w1t[32 * 128];
__device__ unsigned short g_w2t[32 * 32];
__device__ unsigned short g_w3t[8 * 32];

__device__ __forceinline__ unsigned int h2_as_u32(__half2 h) {
    return *reinterpret_cast<unsigned int*>(&h);
}
__device__ __forceinline__ uint32_t f2tf32(float f) {
    uint32_t r;
    asm("cvt.rna.tf32.f32 %0, %1;" : "=r"(r) : "f"(f));
    return r;
}

// ---------------------------------------------------------------- degree + weight preps (fused)
__global__ void k_degree_prep(const int* __restrict__ dst,
                              const float* __restrict__ Wa, const float* __restrict__ Wc,
                              const float* __restrict__ W1, const float* __restrict__ W2,
                              const float* __restrict__ W3) {
    int b = blockIdx.x;
    if (b < FILL_B) {
        int i = b * 256 + threadIdx.x;
        if (i < N_EDGES) atomicAdd(&g_deg[dst[i]], 1);
        return;
    }
    b -= FILL_B;
    if (b < WPREP_B) {
        int idx = b * 256 + threadIdx.x;
        int h = idx >> 14;
        int rem = idx & 16383;
        int n = rem >> 7, k = rem & 127;
        const float* W = h ? Wc : Wa;
        g_wtf[idx] = __uint_as_float(f2tf32(W[k * CCH + n]));
        return;
    }
    b -= WPREP_B;
    int idx = b * 256 + threadIdx.x;
    if (idx < 32 * 128) {
        int n = idx >> 7, k = idx & 127;
        __half h = __float2half(W1[k * 32 + n]);
        g_w1t[idx] = *reinterpret_cast<unsigned short*>(&h);
    } else if (idx < 32 * 128 + 32 * 32) {
        int j = idx - 32 * 128;
        int n = j >> 5, k = j & 31;
        __half h = __float2half(W2[k * 32 + n]);
        g_w2t[j] = *reinterpret_cast<unsigned short*>(&h);
    } else if (idx < 32 * 128 + 32 * 32 + 8 * 32) {
        int j = idx - 32 * 128 - 32 * 32;
        int n = j >> 5, k = j & 31;
        float v = (n < 4) ? W3[k * 4 + n] : 0.f;
        __half h = __float2half(v);
        g_w3t[j] = *reinterpret_cast<unsigned short*>(&h);
    }
}

// ---------------- scans ----------------
__device__ __forceinline__ int block_excl_scan(int v, int lane, int wid, int* warp_sums, int nwarp) {
    int inc = v;
#pragma unroll
    for (int o = 1; o < 32; o <<= 1) {
        int u = __shfl_up_sync(FULLM, inc, o);
        if (lane >= o) inc += u;
    }
    if (lane == 31) warp_sums[wid] = inc;
    __syncthreads();
    if (wid == 0) {
        int w = (lane < nwarp) ? warp_sums[lane] : 0;
#pragma unroll
        for (int o = 1; o < 32; o <<= 1) {
            int u = __shfl_up_sync(FULLM, w, o);
            if (lane >= o) w += u;
        }
        warp_sums[lane] = w;
    }
    __syncthreads();
    return (inc - v) + (wid ? warp_sums[wid - 1] : 0);
}
__global__ void k_scan1() {
    __shared__ int warp_sums[32];
    int i = blockIdx.x * SCAN_B + threadIdx.x;
    int d = 0;
    if (i < N_NODES) {
        d = g_deg[i];
        g_deg[i] = 0;                              // self-clean
        g_dinv[i] = rsqrtf((float)(d + 1));
    }
    int ex = block_excl_scan(d, threadIdx.x & 31, threadIdx.x >> 5, warp_sums, SCAN_B / 32);
    if (i < N_NODES) g_off[i] = ex;
    if (threadIdx.x == SCAN_B - 1) g_bsum[blockIdx.x] = ex + d;
}
__global__ void k_scan3() {
    __shared__ int sbase;
    const int lane = threadIdx.x & 31;
    if (threadIdx.x < 32) {
        int s = 0;
        for (int t = lane; t < blockIdx.x; t += 32) s += g_bsum[t];
#pragma unroll
        for (int o = 16; o > 0; o >>= 1) s += __shfl_xor_sync(FULLM, s, o);
        if (lane == 0) sbase = s;
    }
    __syncthreads();
    int i = blockIdx.x * SCAN_B + threadIdx.x;
    if (i < N_NODES) {
        int o = g_off[i] + sbase;
        g_off[i] = o;
        g_cur[i] = o;
    }
    if (i == 0) g_off[N_NODES] = N_EDGES;
}

// ---------------------------------------------------------------- tf32 mma GEMM (512 thr) + CSR fill
#define KC 64
#define LDT 68
#define SM_A 0                      // 128*68*4 = 34816
#define SM_B 34816
#define SM_TOTAL_MMA (2 * 34816)    // 69632 B

__device__ __forceinline__ void mma16808t(float c[4], const uint32_t a[4], const uint32_t b[2]) {
    asm volatile("mma.sync.aligned.m16n8k8.row.col.f32.tf32.tf32.f32 "
                 "{%0,%1,%2,%3}, {%4,%5,%6,%7}, {%8,%9}, {%0,%1,%2,%3};\n"
                 : "+f"(c[0]), "+f"(c[1]), "+f"(c[2]), "+f"(c[3])
                 : "r"(a[0]), "r"(a[1]), "r"(a[2]), "r"(a[3]), "r"(b[0]), "r"(b[1]));
}
__device__ __forceinline__ void mma16816h(float c[4], const uint32_t a[4], const uint32_t b[2]) {
    asm volatile("mma.sync.aligned.m16n8k16.row.col.f32.f16.f16.f32 "
                 "{%0,%1,%2,%3}, {%4,%5,%6,%7}, {%8,%9}, {%0,%1,%2,%3};\n"
                 : "+f"(c[0]), "+f"(c[1]), "+f"(c[2]), "+f"(c[3])
                 : "r"(a[0]), "r"(a[1]), "r"(a[2]), "r"(a[3]), "r"(b[0]), "r"(b[1]));
}

__global__ __launch_bounds__(512, 2)
void k_gemm_fill(const float* __restrict__ x,
                 const int* __restrict__ src,
                 const int* __restrict__ dst)
{
    if (blockIdx.x >= 2 * GEMM_BX) {
        int e = (blockIdx.x - 2 * GEMM_BX) * 512 + threadIdx.x;
        if (e < N_EDGES) {
            int d = dst[e];
            int p = atomicAdd(&g_cur[d], 1);
            g_csr[p] = src[e];
        }
        return;
    }

    extern __shared__ char smem[];
    uint32_t* smA = reinterpret_cast<uint32_t*>(smem + SM_A);
    uint32_t* smB = reinterpret_cast<uint32_t*>(smem + SM_B);
    const int tid  = threadIdx.x;
    const int wid  = tid >> 5, lane = tid & 31;
    const int half = (blockIdx.x >= GEMM_BX) ? 1 : 0;
    const int bm   = (blockIdx.x - half * GEMM_BX) * 128;
    const int wm   = wid & 3;        // 32-row group (0..3)
    const int wn   = wid >> 2;       // 32-col group (0..3)
    const int lq   = lane >> 2;      // 0..7
    const int lr   = lane & 3;       // 0..3

    float acc[2][4][4];
#pragma unroll
    for (int i = 0; i < 2; i++)
#pragma unroll
        for (int j = 0; j < 4; j++)
#pragma unroll
            for (int q = 0; q < 4; q++) acc[i][j][q] = 0.f;

    for (int kc = 0; kc < CCH; kc += KC) {
        // A tile: 128 rows x 64 cols fp32 -> tf32 (2048 float4 slots)
        for (int g = tid; g < 2048; g += 512) {
            int row = g >> 4, c4 = (g & 15) * 4;
            float4 v = make_float4(0.f, 0.f, 0.f, 0.f);
            if (bm + row < N_NODES)
                v = *reinterpret_cast<const float4*>(&x[(size_t)(bm + row) * CCH + kc + c4]);
            uint32_t* p = &smA[row * LDT + c4];
            p[0] = f2tf32(v.x); p[1] = f2tf32(v.y); p[2] = f2tf32(v.z); p[3] = f2tf32(v.w);
        }
        // B tile: 128 n x 64 k (tf32-rounded)
        for (int g = tid; g < 2048; g += 512) {
            int n = g >> 4, c4 = (g & 15) * 4;
            const float4 v = *reinterpret_cast<const float4*>(
                &g_wtf[((size_t)(half * 128 + n)) * 128 + kc + c4]);
            uint32_t* p = &smB[n * LDT + c4];
            p[0] = __float_as_uint(v.x); p[1] = __float_as_uint(v.y);
            p[2] = __float_as_uint(v.z); p[3] = __float_as_uint(v.w);
        }
        __syncthreads();

#pragma unroll
        for (int ks = 0; ks < KC / 8; ks++) {
            const int k8 = ks * 8;
            uint32_t a[2][4];
#pragma unroll
            for (int ma = 0; ma < 2; ma++) {
                int r0 = wm * 32 + ma * 16 + lq;
                a[ma][0] = smA[r0 * LDT + k8 + lr];
                a[ma][1] = smA[(r0 + 8) * LDT + k8 + lr];
                a[ma][2] = smA[r0 * LDT + k8 + lr + 4];
                a[ma][3] = smA[(r0 + 8) * LDT + k8 + lr + 4];
            }
#pragma unroll
            for (int nb = 0; nb < 4; nb++) {
                int n = wn * 32 + nb * 8 + lq;
                uint32_t b[2];
                b[0] = smB[n * LDT + k8 + lr];
                b[1] = smB[n * LDT + k8 + lr + 4];
#pragma unroll
                for (int ma = 0; ma < 2; ma++) mma16808t(acc[ma][nb], a[ma], b);
            }
        }
        __syncthreads();
    }

    unsigned char* fb = reinterpret_cast<unsigned char*>(g_feat_h);
#pragma unroll
    for (int ma = 0; ma < 2; ma++) {
        int row0 = bm + wm * 32 + ma * 16 + lq;
        int row1 = row0 + 8;
        float dv0 = (row0 < N_NODES) ? g_dinv[row0] : 0.f;
        float dv1 = (row1 < N_NODES) ? g_dinv[row1] : 0.f;
#pragma unroll
        for (int nb = 0; nb < 4; nb++) {
            int cpair = wn * 16 + nb * 4 + lr;      // 0..63 (pair of channels)
            uint32_t cb = (uint32_t)(cpair >> 1) * 16 + (uint32_t)half * 8 + (cpair & 1) * 4;
            if (row0 < N_NODES) {
                *reinterpret_cast<uint32_t*>(fb + (size_t)row0 * 512 + cb) =
                    h2_as_u32(__floats2half2_rn(acc[ma][nb][0] * dv0, acc[ma][nb][1] * dv0));
            }
            if (row1 < N_NODES) {
                *reinterpret_cast<uint32_t*>(fb + (size_t)row1 * 512 + cb) =
                    h2_as_u32(__floats2half2_rn(acc[ma][nb][2] * dv1, acc[ma][nb][3] * dv1));
            }
        }
    }
}

// ---------------------------------------------------------------- gather + conv epilogue
__device__ __forceinline__ void addh(float4& A, float4& Cc, uint4 v) {
    float2 f0 = __half22float2(*reinterpret_cast<__half2*>(&v.x));
    float2 f1 = __half22float2(*reinterpret_cast<__half2*>(&v.y));
    float2 f2 = __half22float2(*reinterpret_cast<__half2*>(&v.z));
    float2 f3 = __half22float2(*reinterpret_cast<__half2*>(&v.w));
    A.x += f0.x; A.y += f0.y; A.z += f1.x; A.w += f1.y;
    Cc.x += f2.x; Cc.y += f2.y; Cc.z += f3.x; Cc.w += f3.y;
}

__global__ __launch_bounds__(256)
void k_aggregate(const float* __restrict__ x,
                 const float* __restrict__ a_conv_b,
                 const float* __restrict__ c_conv_b)
{
    __shared__ float sab[CCH], scb[CCH];
    __shared__ float scsum[CCH];

    const int tid = threadIdx.x;
    if (tid < 128) { sab[tid] = a_conv_b[tid]; scb[tid] = c_conv_b[tid]; scsum[tid] = 0.f; }
    __syncthreads();

    const int lane = tid & 31;
    const int warp = tid >> 5;
    const int gw = blockIdx.x * (blockDim.x >> 5) + warp;
    const int nw = gridDim.x * (blockDim.x >> 5);

    float4 cs = make_float4(0.f, 0.f, 0.f, 0.f);
    uint2* atab = reinterpret_cast<uint2*>(g_atab);

    for (int node = gw; node < N_NODES; node += nw) {
        const float dv = g_dinv[node];
        float4 A  = make_float4(0.f, 0.f, 0.f, 0.f);
        float4 Cc = make_float4(0.f, 0.f, 0.f, 0.f);
        addh(A, Cc, g_feat_h[(size_t)node * 32 + lane]);     // self loop

        const int beg = g_off[node], end = g_off[node + 1];
        int j = beg;
        for (; j + 3 < end; j += 4) {
            int s0 = g_csr[j], s1 = g_csr[j + 1], s2 = g_csr[j + 2], s3 = g_csr[j + 3];
            uint4 v0 = g_feat_h[(size_t)s0 * 32 + lane];
            uint4 v1 = g_feat_h[(size_t)s1 * 32 + lane];
            uint4 v2 = g_feat_h[(size_t)s2 * 32 + lane];
            uint4 v3 = g_feat_h[(size_t)s3 * 32 + lane];
            addh(A, Cc, v0); addh(A, Cc, v1); addh(A, Cc, v2); addh(A, Cc, v3);
        }
        for (; j < end; j++) {
            uint4 v0 = g_feat_h[(size_t)g_csr[j] * 32 + lane];
            addh(A, Cc, v0);
        }

        float4 xv = reinterpret_cast<const float4*>(x)[(size_t)node * 32 + lane];
        int c0 = 4 * lane;
        float4 a;
        a.x = fmaxf(fmaf(A.x, dv, sab[c0 + 0]), 0.f) + xv.x;
        a.y = fmaxf(fmaf(A.y, dv, sab[c0 + 1]), 0.f) + xv.y;
        a.z = fmaxf(fmaf(A.z, dv, sab[c0 + 2]), 0.f) + xv.z;
        a.w = fmaxf(fmaf(A.w, dv, sab[c0 + 3]), 0.f) + xv.w;

        uint2 av;
        av.x = h2_as_u32(__floats2half2_rn(a.x, a.y));
        av.y = h2_as_u32(__floats2half2_rn(a.z, a.w));
        atab[(size_t)node * 32 + lane] = av;

        cs.x += fmaxf(fmaf(Cc.x, dv, scb[c0 + 0]), 0.f) + xv.x;
        cs.y += fmaxf(fmaf(Cc.y, dv, scb[c0 + 1]), 0.f) + xv.y;
        cs.z += fmaxf(fmaf(Cc.z, dv, scb[c0 + 2]), 0.f) + xv.z;
        cs.w += fmaxf(fmaf(Cc.w, dv, scb[c0 + 3]), 0.f) + xv.w;
    }

    int c0 = 4 * lane;
    atomicAdd(&scsum[c0 + 0], cs.x);
    atomicAdd(&scsum[c0 + 1], cs.y);
    atomicAdd(&scsum[c0 + 2], cs.z);
    atomicAdd(&scsum[c0 + 3], cs.w);
    __syncthreads();
    if (tid < CCH) atomicAdd(&g_csum[tid], scsum[tid]);
}

// ---------------------------------------------------------------- actor MLP via mma.sync (+ critic head block)
#define MLP_LDA 136
#define MLP_LDH 40
#define OFF_A  0
#define OFF_H1 34816
#define OFF_H2 45056
#define OFF_W1 55296
#define OFF_W2 64000
#define OFF_W3 66560
#define OFF_B  67200
#define MLP_SMEM 67584

__device__ __forceinline__ float softplus_f(float v) {
    return fmaxf(v, 0.f) + log1pf(expf(-fabsf(v))) + 1e-20f;
}

__global__ __launch_bounds__(128)
void k_mlp(const float* __restrict__ b1, const float* __restrict__ b2,
           const float* __restrict__ b3,
           const float* __restrict__ cW1, const float* __restrict__ cb1,
           const float* __restrict__ cW2, const float* __restrict__ cb2,
           const float* __restrict__ cW3, const float* __restrict__ cb3,
           float* __restrict__ out)
{
    // last block: critic value head (one warp), self-cleans g_csum
    if (blockIdx.x == GEMM_BX) {
        const int lane = threadIdx.x;
        if (lane >= 32) return;
        float c0 = g_csum[lane], c1 = g_csum[lane + 32],
              c2 = g_csum[lane + 64], c3 = g_csum[lane + 96];
        g_csum[lane] = 0.f; g_csum[lane + 32] = 0.f;
        g_csum[lane + 64] = 0.f; g_csum[lane + 96] = 0.f;
        float h1 = cb1[lane];
#pragma unroll
        for (int r = 0; r < 32; r++)
            h1 = fmaf(__shfl_sync(FULLM, c0, r), cW1[(r      ) * 32 + lane], h1);
#pragma unroll
        for (int r = 0; r < 32; r++)
            h1 = fmaf(__shfl_sync(FULLM, c1, r), cW1[(r + 32 ) * 32 + lane], h1);
#pragma unroll
        for (int r = 0; r < 32; r++)
            h1 = fmaf(__shfl_sync(FULLM, c2, r), cW1[(r + 64 ) * 32 + lane], h1);
#pragma unroll
        for (int r = 0; r < 32; r++)
            h1 = fmaf(__shfl_sync(FULLM, c3, r), cW1[(r + 96 ) * 32 + lane], h1);
        h1 = fmaxf(h1, 0.f);
        float h2 = cb2[lane];
#pragma unroll
        for (int r = 0; r < 32; r++)
            h2 = fmaf(__shfl_sync(FULLM, h1, r), cW2[r * 32 + lane], h2);
        h2 = fmaxf(h2, 0.f);
        float p = h2 * cW3[lane];
#pragma unroll
        for (int off = 16; off > 0; off >>= 1)
            p += __shfl_xor_sync(FULLM, p, off);
        if (lane == 0) out[(size_t)4 * N_NODES] = p + cb3[0];
        return;
    }

    extern __shared__ char sm[];
    const int tid = threadIdx.x;
    const int w = tid >> 5, lane = tid & 31;
    const int lq = lane >> 2, lr = lane & 3;
    const int bm = blockIdx.x * 128;

    float* fb1 = reinterpret_cast<float*>(sm + OFF_B);
    float* fb2 = fb1 + 32;
    float* fb3 = fb2 + 32;

    for (int g = tid; g < 32 * 64; g += 128) {
        int n = g >> 6, k2 = g & 63;
        *reinterpret_cast<uint32_t*>(sm + OFF_W1 + n * (MLP_LDA * 2) + k2 * 4) =
            reinterpret_cast<const uint32_t*>(g_w1t)[n * 64 + k2];
    }
    for (int g = tid; g < 32 * 16; g += 128) {
        int n = g >> 4, k2 = g & 15;
        *reinterpret_cast<uint32_t*>(sm + OFF_W2 + n * (MLP_LDH * 2) + k2 * 4) =
            reinterpret_cast<const uint32_t*>(g_w2t)[n * 16 + k2];
    }
    if (tid < 128) {
        int n = tid >> 4, k2 = tid & 15;
        *reinterpret_cast<uint32_t*>(sm + OFF_W3 + n * (MLP_LDH * 2) + k2 * 4) =
            reinterpret_cast<const uint32_t*>(g_w3t)[n * 16 + k2];
    }
    if (tid < 32) { fb1[tid] = b1[tid]; fb2[tid] = b2[tid]; }
    if (tid < 4)  { fb3[tid] = b3[tid]; }
    for (int g = tid; g < 128 * 16; g += 128) {
        int row = g >> 4, q = g & 15;
        uint4 v = make_uint4(0u, 0u, 0u, 0u);
        if (bm + row < N_NODES) v = g_atab[(size_t)(bm + row) * 16 + q];
        *reinterpret_cast<uint4*>(sm + OFF_A + row * (MLP_LDA * 2) + q * 16) = v;
    }
    __syncthreads();

    float acc1[2][4][4];
#pragma unroll
    for (int i = 0; i < 2; i++)
#pragma unroll
        for (int j = 0; j < 4; j++)
#pragma unroll
            for (int q = 0; q < 4; q++) acc1[i][j][q] = 0.f;

#pragma unroll
    for (int ks = 0; ks < 8; ks++) {
        uint32_t a[2][4];
#pragma unroll
        for (int ma = 0; ma < 2; ma++) {
            int row = w * 32 + ma * 16 + lq;
            uint32_t o = OFF_A + row * (MLP_LDA * 2) + (ks * 16 + lr * 2) * 2;
            a[ma][0] = *reinterpret_cast<uint32_t*>(sm + o);
            a[ma][1] = *reinterpret_cast<uint32_t*>(sm + o + 8 * (MLP_LDA * 2));
            a[ma][2] = *reinterpret_cast<uint32_t*>(sm + o + 16);
            a[ma][3] = *reinterpret_cast<uint32_t*>(sm + o + 8 * (MLP_LDA * 2) + 16);
        }
#pragma unroll
        for (int nb = 0; nb < 4; nb++) {
            int n = nb * 8 + lq;
            uint32_t o = OFF_W1 + n * (MLP_LDA * 2) + (ks * 16 + lr * 2) * 2;
            uint32_t b[2];
            b[0] = *reinterpret_cast<uint32_t*>(sm + o);
            b[1] = *reinterpret_cast<uint32_t*>(sm + o + 16);
#pragma unroll
            for (int ma = 0; ma < 2; ma++) mma16816h(acc1[ma][nb], a[ma], b);
        }
    }
#pragma unroll
    for (int ma = 0; ma < 2; ma++) {
        int row = w * 32 + ma * 16 + lq;
#pragma unroll
        for (int nb = 0; nb < 4; nb++) {
            int col = nb * 8 + lr * 2;
            float v0 = fmaxf(acc1[ma][nb][0] + fb1[col], 0.f);
            float v1 = fmaxf(acc1[ma][nb][1] + fb1[col + 1], 0.f);
            float v2 = fmaxf(acc1[ma][nb][2] + fb1[col], 0.f);
            float v3 = fmaxf(acc1[ma][nb][3] + fb1[col + 1], 0.f);
            *reinterpret_cast<uint32_t*>(sm + OFF_H1 + row * (MLP_LDH * 2) + col * 2) =
                h2_as_u32(__floats2half2_rn(v0, v1));
            *reinterpret_cast<uint32_t*>(sm + OFF_H1 + (row + 8) * (MLP_LDH * 2) + col * 2) =
                h2_as_u32(__floats2half2_rn(v2, v3));
        }
    }
    __syncwarp();

    float acc2[2][4][4];
#pragma unroll
    for (int i = 0; i < 2; i++)
#pragma unroll
        for (int j = 0; j < 4; j++)
#pragma unroll
            for (int q = 0; q < 4; q++) acc2[i][j][q] = 0.f;
#pragma unroll
    for (int ks = 0; ks < 2; ks++) {
        uint32_t a[2][4];
#pragma unroll
        for (int ma = 0; ma < 2; ma++) {
            int row = w * 32 + ma * 16 + lq;
            uint32_t o = OFF_H1 + row * (MLP_LDH * 2) + (ks * 16 + lr * 2) * 2;
            a[ma][0] = *reinterpret_cast<uint32_t*>(sm + o);
            a[ma][1] = *reinterpret_cast<uint32_t*>(sm + o + 8 * (MLP_LDH * 2));
            a[ma][2] = *reinterpret_cast<uint32_t*>(sm + o + 16);
            a[ma][3] = *reinterpret_cast<uint32_t*>(sm + o + 8 * (MLP_LDH * 2) + 16);
        }
#pragma unroll
        for (int nb = 0; nb < 4; nb++) {
            int n = nb * 8 + lq;
            uint32_t o = OFF_W2 + n * (MLP_LDH * 2) + (ks * 16 + lr * 2) * 2;
            uint32_t b[2];
            b[0] = *reinterpret_cast<uint32_t*>(sm + o);
            b[1] = *reinterpret_cast<uint32_t*>(sm + o + 16);
#pragma unroll
            for (int ma = 0; ma < 2; ma++) mma16816h(acc2[ma][nb], a[ma], b);
        }
    }
#pragma unroll
    for (int ma = 0; ma < 2; ma++) {
        int row = w * 32 + ma * 16 + lq;
#pragma unroll
        for (int nb = 0; nb < 4; nb++) {
            int col = nb * 8 + lr * 2;
            float v0 = fmaxf(acc2[ma][nb][0] + fb2[col], 0.f);
            float v1 = fmaxf(acc2[ma][nb][1] + fb2[col + 1], 0.f);
            float v2 = fmaxf(acc2[ma][nb][2] + fb2[col], 0.f);
            float v3 = fmaxf(acc2[ma][nb][3] + fb2[col + 1], 0.f);
            *reinterpret_cast<uint32_t*>(sm + OFF_H2 + row * (MLP_LDH * 2) + col * 2) =
                h2_as_u32(__floats2half2_rn(v0, v1));
            *reinterpret_cast<uint32_t*>(sm + OFF_H2 + (row + 8) * (MLP_LDH * 2) + col * 2) =
                h2_as_u32(__floats2half2_rn(v2, v3));
        }
    }
    __syncwarp();

    float acc3[2][4];
#pragma unroll
    for (int i = 0; i < 2; i++)
#pragma unroll
        for (int q = 0; q < 4; q++) acc3[i][q] = 0.f;
#pragma unroll
    for (int ks = 0; ks < 2; ks++) {
        uint32_t a[2][4];
#pragma unroll
        for (int ma = 0; ma < 2; ma++) {
            int row = w * 32 + ma * 16 + lq;
            uint32_t o = OFF_H2 + row * (MLP_LDH * 2) + (ks * 16 + lr * 2) * 2;
            a[ma][0] = *reinterpret_cast<uint32_t*>(sm + o);
            a[ma][1] = *reinterpret_cast<uint32_t*>(sm + o + 8 * (MLP_LDH * 2));
            a[ma][2] = *reinterpret_cast<uint32_t*>(sm + o + 16);
            a[ma][3] = *reinterpret_cast<uint32_t*>(sm + o + 8 * (MLP_LDH * 2) + 16);
        }
        int n = lq;
        uint32_t o = OFF_W3 + n * (MLP_LDH * 2) + (ks * 16 + lr * 2) * 2;
        uint32_t b[2];
        b[0] = *reinterpret_cast<uint32_t*>(sm + o);
        b[1] = *reinterpret_cast<uint32_t*>(sm + o + 16);
#pragma unroll
        for (int ma = 0; ma < 2; ma++) mma16816h(acc3[ma], a[ma], b);
    }
    if (lr < 2) {
        int ca = 2 * lr, cb = 2 * lr + 1;
#pragma unroll
        for (int ma = 0; ma < 2; ma++) {
            int r0 = bm + w * 32 + ma * 16 + lq;
            int r1 = r0 + 8;
            if (r0 < N_NODES) {
                float s0 = softplus_f(acc3[ma][0] + fb3[ca]);
                float s1 = softplus_f(acc3[ma][1] + fb3[cb]);
                if (ca == 0) out[r0] = s0; else out[N_NODES + (size_t)r0 * 3 + ca - 1] = s0;
                out[N_NODES + (size_t)r0 * 3 + cb - 1] = s1;
            }
            if (r1 < N_NODES) {
                float s2 = softplus_f(acc3[ma][2] + fb3[ca]);
                float s3 = softplus_f(acc3[ma][3] + fb3[cb]);
                if (ca == 0) out[r1] = s2; else out[N_NODES + (size_t)r1 * 3 + ca - 1] = s2;
                out[N_NODES + (size_t)r1 * 3 + cb - 1] = s3;
            }
        }
    }
}

// ---------------------------------------------------------------- launch
extern "C" void kernel_launch(void* const* d_in, const int* in_sizes, int n_in,
                              void* d_out, int out_size)
{
    const float* x    = (const float*)d_in[0];
    const int*   ei   = (const int*)  d_in[1];
    const float* aW   = (const float*)d_in[2];
    const float* ab   = (const float*)d_in[3];
    const float* aW1  = (const float*)d_in[4];
    const float* ab1  = (const float*)d_in[5];
    const float* aW2  = (const float*)d_in[6];
    const float* ab2  = (const float*)d_in[7];
    const float* aW3  = (const float*)d_in[8];
    const float* ab3  = (const float*)d_in[9];
    const float* cW   = (const float*)d_in[10];
    const float* cb   = (const float*)d_in[11];
    const float* cW1  = (const float*)d_in[12];
    const float* cb1  = (const float*)d_in[13];
    const float* cW2  = (const float*)d_in[14];
    const float* cb2  = (const float*)d_in[15];
    const float* cW3  = (const float*)d_in[16];
    const float* cb3  = (const float*)d_in[17];
    float* out = (float*)d_out;

    const int* src = ei;
    const int* dst = ei + N_EDGES;

    cudaFuncSetAttribute((const void*)k_gemm_fill,
                         cudaFuncAttributeMaxDynamicSharedMemorySize, SM_TOTAL_MMA);
    cudaFuncSetAttribute((const void*)k_mlp,
                         cudaFuncAttributeMaxDynamicSharedMemorySize, MLP_SMEM);

    k_degree_prep<<<FILL_B + WPREP_B + MLPP_B, 256>>>(dst, aW, cW, aW1, aW2, aW3);
    k_scan1      <<<SCAN_G, SCAN_B>>>();
    k_scan3      <<<SCAN_G, SCAN_B>>>();

    k_gemm_fill<<<2 * GEMM_BX + FILL_B5, 512, SM_TOTAL_MMA>>>(x, src, dst);

    k_aggregate<<<2048, 256>>>(x, ab, cb);

    k_mlp<<<GEMM_BX + 1, 128, MLP_SMEM>>>(ab1, ab2, ab3,
                                          cW1, cb1, cW2, cb2, cW3, cb3, out);
}

// round 16
// speedup vs baseline: 1.2562x; 1.2562x over previous
#include <cuda_runtime.h>
#include <cuda_fp16.h>
#include <stdint.h>
#include <math.h>

#define N_NODES 100000
#define N_EDGES 1600000
#define CCH 128
#define FULLM 0xffffffffu
#define SCAN_B 1024
#define SCAN_G ((N_NODES + SCAN_B - 1) / SCAN_B)   // 98
#define GEMM_BX ((N_NODES + 127) / 128)            // 782
#define FILL_B  ((N_EDGES + 255) / 256)            // 6250
#define WPREP_B 128
#define MLPP_B  21

// ---------------- device scratch (zero-initialized at load; kernels self-clean) ----------------
__device__ uint4 g_feat_h[(size_t)N_NODES * 32];
__device__ uint4 g_atab[(size_t)N_NODES * 16];
__device__ int   g_deg [N_NODES];
__device__ float g_dinv[N_NODES];
__device__ int   g_off [N_NODES + 1];
__device__ int   g_cur [N_NODES];
__device__ int   g_csr [N_EDGES];
__device__ int   g_bsum[SCAN_G];
__device__ float g_csum[CCH];
__device__ float g_wtf[2 * CCH * CCH];             // W^T tf32, k pair-interleaved within 8-groups
__device__ unsigned short g_w1t[32 * 128];
__device__ unsigned short g_w2t[32 * 32];
__device__ unsigned short g_w3t[8 * 32];

__device__ __forceinline__ unsigned int h2_as_u32(__half2 h) {
    return *reinterpret_cast<unsigned int*>(&h);
}
__device__ __forceinline__ uint32_t f2tf32(float f) {
    uint32_t r;
    asm("cvt.rna.tf32.f32 %0, %1;" : "=r"(r) : "f"(f));
    return r;
}
// pair-interleave within 8-group: j<4 -> 2j ; j>=4 -> 2(j-4)+1
__device__ __forceinline__ int kperm(int k) {
    int j = k & 7;
    int s = (j < 4) ? (2 * j) : (2 * (j - 4) + 1);
    return (k & ~7) + s;
}

// ---------------------------------------------------------------- degree + weight preps (fused)
__global__ void k_degree_prep(const int* __restrict__ dst,
                              const float* __restrict__ Wa, const float* __restrict__ Wc,
                              const float* __restrict__ W1, const float* __restrict__ W2,
                              const float* __restrict__ W3) {
    int b = blockIdx.x;
    if (b < FILL_B) {
        int i = b * 256 + threadIdx.x;
        if (i < N_EDGES) atomicAdd(&g_deg[dst[i]], 1);
        return;
    }
    b -= FILL_B;
    if (b < WPREP_B) {
        int idx = b * 256 + threadIdx.x;          // < 32768
        int h = idx >> 14;
        int rem = idx & 16383;
        int n = rem >> 7, k = rem & 127;
        const float* W = h ? Wc : Wa;
        // store at permuted k position so B staging is a straight copy
        g_wtf[(idx & ~127) + kperm(k)] = __uint_as_float(f2tf32(W[k * CCH + n]));
        return;
    }
    b -= WPREP_B;
    int idx = b * 256 + threadIdx.x;
    if (idx < 32 * 128) {
        int n = idx >> 7, k = idx & 127;
        __half h = __float2half(W1[k * 32 + n]);
        g_w1t[idx] = *reinterpret_cast<unsigned short*>(&h);
    } else if (idx < 32 * 128 + 32 * 32) {
        int j = idx - 32 * 128;
        int n = j >> 5, k = j & 31;
        __half h = __float2half(W2[k * 32 + n]);
        g_w2t[j] = *reinterpret_cast<unsigned short*>(&h);
    } else if (idx < 32 * 128 + 32 * 32 + 8 * 32) {
        int j = idx - 32 * 128 - 32 * 32;
        int n = j >> 5, k = j & 31;
        float v = (n < 4) ? W3[k * 4 + n] : 0.f;
        __half h = __float2half(v);
        g_w3t[j] = *reinterpret_cast<unsigned short*>(&h);
    }
}

// ---------------- scans (merged 2-phase; self-cleaning) ----------------
__device__ __forceinline__ int block_excl_scan(int v, int lane, int wid, int* warp_sums, int nwarp) {
    int inc = v;
#pragma unroll
    for (int o = 1; o < 32; o <<= 1) {
        int u = __shfl_up_sync(FULLM, inc, o);
        if (lane >= o) inc += u;
    }
    if (lane == 31) warp_sums[wid] = inc;
    __syncthreads();
    if (wid == 0) {
        int w = (lane < nwarp) ? warp_sums[lane] : 0;
#pragma unroll
        for (int o = 1; o < 32; o <<= 1) {
            int u = __shfl_up_sync(FULLM, w, o);
            if (lane >= o) w += u;
        }
        warp_sums[lane] = w;
    }
    __syncthreads();
    return (inc - v) + (wid ? warp_sums[wid - 1] : 0);
}
__global__ void k_scan1() {
    __shared__ int warp_sums[32];
    int i = blockIdx.x * SCAN_B + threadIdx.x;
    int d = 0;
    if (i < N_NODES) {
        d = g_deg[i];
        g_deg[i] = 0;                              // self-clean for graph replay
        g_dinv[i] = rsqrtf((float)(d + 1));
    }
    int ex = block_excl_scan(d, threadIdx.x & 31, threadIdx.x >> 5, warp_sums, SCAN_B / 32);
    if (i < N_NODES) g_off[i] = ex;
    if (threadIdx.x == SCAN_B - 1) g_bsum[blockIdx.x] = ex + d;
}
__global__ void k_scan3() {
    __shared__ int sbase;
    const int lane = threadIdx.x & 31;
    if (threadIdx.x < 32) {
        int s = 0;
        for (int t = lane; t < blockIdx.x; t += 32) s += g_bsum[t];
#pragma unroll
        for (int o = 16; o > 0; o >>= 1) s += __shfl_xor_sync(FULLM, s, o);
        if (lane == 0) sbase = s;
    }
    __syncthreads();
    int i = blockIdx.x * SCAN_B + threadIdx.x;
    if (i < N_NODES) {
        int o = g_off[i] + sbase;
        g_off[i] = o;
        g_cur[i] = o;
    }
    if (i == 0) g_off[N_NODES] = N_EDGES;
}

// ---------------------------------------------------------------- tf32 mma GEMM + CSR fill
// 256 thr, KC=64, k pair-interleaved smem, LDS.64 fragment loads.
#define KC 64
#define LDT 72                      // floats; 72 mod 32 = 8 -> clean stripes for LDS.64
#define SM_A 0                      // 128*72*4 = 36864
#define SM_B 36864
#define SM_TOTAL_MMA (2 * 36864)    // 73728 B

__device__ __forceinline__ void mma16808t(float c[4], const uint32_t a[4], const uint32_t b[2]) {
    asm volatile("mma.sync.aligned.m16n8k8.row.col.f32.tf32.tf32.f32 "
                 "{%0,%1,%2,%3}, {%4,%5,%6,%7}, {%8,%9}, {%0,%1,%2,%3};\n"
                 : "+f"(c[0]), "+f"(c[1]), "+f"(c[2]), "+f"(c[3])
                 : "r"(a[0]), "r"(a[1]), "r"(a[2]), "r"(a[3]), "r"(b[0]), "r"(b[1]));
}
__device__ __forceinline__ void mma16816h(float c[4], const uint32_t a[4], const uint32_t b[2]) {
    asm volatile("mma.sync.aligned.m16n8k16.row.col.f32.f16.f16.f32 "
                 "{%0,%1,%2,%3}, {%4,%5,%6,%7}, {%8,%9}, {%0,%1,%2,%3};\n"
                 : "+f"(c[0]), "+f"(c[1]), "+f"(c[2]), "+f"(c[3])
                 : "r"(a[0]), "r"(a[1]), "r"(a[2]), "r"(a[3]), "r"(b[0]), "r"(b[1]));
}

__global__ __launch_bounds__(256)
void k_gemm_fill(const float* __restrict__ x,
                 const int* __restrict__ src,
                 const int* __restrict__ dst)
{
    if (blockIdx.x >= 2 * GEMM_BX) {
        int e = (blockIdx.x - 2 * GEMM_BX) * 256 + threadIdx.x;
        if (e < N_EDGES) {
            int d = dst[e];
            int p = atomicAdd(&g_cur[d], 1);
            g_csr[p] = src[e];
        }
        return;
    }

    extern __shared__ char smem[];
    float* smA = reinterpret_cast<float*>(smem + SM_A);
    float* smB = reinterpret_cast<float*>(smem + SM_B);
    const int tid  = threadIdx.x;
    const int wid  = tid >> 5, lane = tid & 31;
    const int half = (blockIdx.x >= GEMM_BX) ? 1 : 0;
    const int bm   = (blockIdx.x - half * GEMM_BX) * 128;
    const int wm   = wid & 3;        // 32-row group
    const int wn   = wid >> 2;       // 64-col group
    const int lq   = lane >> 2;      // 0..7
    const int lr   = lane & 3;       // 0..3

    float acc[2][8][4];
#pragma unroll
    for (int i = 0; i < 2; i++)
#pragma unroll
        for (int j = 0; j < 8; j++)
#pragma unroll
            for (int q = 0; q < 4; q++) acc[i][j][q] = 0.f;

    for (int kc = 0; kc < CCH; kc += KC) {
        // A tile: pair-interleave on the fly; still 2 STS.128 per 8 source floats.
        for (int g = tid; g < 1024; g += 256) {
            int row = g >> 3, c8 = (g & 7) * 8;
            float4 v0 = make_float4(0.f, 0.f, 0.f, 0.f);
            float4 v1 = v0;
            if (bm + row < N_NODES) {
                const float4* xp = reinterpret_cast<const float4*>(
                    &x[(size_t)(bm + row) * CCH + kc + c8]);
                v0 = xp[0]; v1 = xp[1];
            }
            float* p = &smA[row * LDT + c8];
            // slots: (j0,j4,j1,j5) then (j2,j6,j3,j7), tf32-rounded
            float4 w0, w1;
            w0.x = __uint_as_float(f2tf32(v0.x)); w0.y = __uint_as_float(f2tf32(v1.x));
            w0.z = __uint_as_float(f2tf32(v0.y)); w0.w = __uint_as_float(f2tf32(v1.y));
            w1.x = __uint_as_float(f2tf32(v0.z)); w1.y = __uint_as_float(f2tf32(v1.z));
            w1.z = __uint_as_float(f2tf32(v0.w)); w1.w = __uint_as_float(f2tf32(v1.w));
            *reinterpret_cast<float4*>(p)     = w0;
            *reinterpret_cast<float4*>(p + 4) = w1;
        }
        // B tile: already permuted in g_wtf -> straight copy
        for (int g = tid; g < 1024; g += 256) {
            int n = g >> 3, c8 = (g & 7) * 8;
            const float4* wp = reinterpret_cast<const float4*>(
                &g_wtf[((size_t)(half * 128 + n)) * 128 + kc + c8]);
            float* p = &smB[n * LDT + c8];
            *reinterpret_cast<float4*>(p)     = wp[0];
            *reinterpret_cast<float4*>(p + 4) = wp[1];
        }
        __syncthreads();

#pragma unroll
        for (int ks = 0; ks < KC / 8; ks++) {
            const int k8 = ks * 8;
            uint32_t a[2][4];
#pragma unroll
            for (int ma = 0; ma < 2; ma++) {
                int r0 = wm * 32 + ma * 16 + lq;
                float2 lo = *reinterpret_cast<const float2*>(&smA[r0 * LDT + k8 + 2 * lr]);
                float2 hi = *reinterpret_cast<const float2*>(&smA[(r0 + 8) * LDT + k8 + 2 * lr]);
                a[ma][0] = __float_as_uint(lo.x);   // A[r0][k_lo]
                a[ma][1] = __float_as_uint(hi.x);   // A[r0+8][k_lo]
                a[ma][2] = __float_as_uint(lo.y);   // A[r0][k_hi]
                a[ma][3] = __float_as_uint(hi.y);   // A[r0+8][k_hi]
            }
#pragma unroll
            for (int nb = 0; nb < 8; nb++) {
                int n = wn * 64 + nb * 8 + lq;
                float2 bb = *reinterpret_cast<const float2*>(&smB[n * LDT + k8 + 2 * lr]);
                uint32_t b[2];
                b[0] = __float_as_uint(bb.x);
                b[1] = __float_as_uint(bb.y);
#pragma unroll
                for (int ma = 0; ma < 2; ma++) mma16808t(acc[ma][nb], a[ma], b);
            }
        }
        __syncthreads();
    }

    unsigned char* fb = reinterpret_cast<unsigned char*>(g_feat_h);
#pragma unroll
    for (int ma = 0; ma < 2; ma++) {
        int row0 = bm + wm * 32 + ma * 16 + lq;
        int row1 = row0 + 8;
        float dv0 = (row0 < N_NODES) ? g_dinv[row0] : 0.f;
        float dv1 = (row1 < N_NODES) ? g_dinv[row1] : 0.f;
#pragma unroll
        for (int nb = 0; nb < 8; nb++) {
            int cpair = wn * 32 + nb * 4 + lr;
            uint32_t cb = (uint32_t)(cpair >> 1) * 16 + (uint32_t)half * 8 + (cpair & 1) * 4;
            if (row0 < N_NODES) {
                *reinterpret_cast<uint32_t*>(fb + (size_t)row0 * 512 + cb) =
                    h2_as_u32(__floats2half2_rn(acc[ma][nb][0] * dv0, acc[ma][nb][1] * dv0));
            }
            if (row1 < N_NODES) {
                *reinterpret_cast<uint32_t*>(fb + (size_t)row1 * 512 + cb) =
                    h2_as_u32(__floats2half2_rn(acc[ma][nb][2] * dv1, acc[ma][nb][3] * dv1));
            }
        }
    }
}

// ---------------------------------------------------------------- gather + conv epilogue
__device__ __forceinline__ void addh(float4& A, float4& Cc, uint4 v) {
    float2 f0 = __half22float2(*reinterpret_cast<__half2*>(&v.x));
    float2 f1 = __half22float2(*reinterpret_cast<__half2*>(&v.y));
    float2 f2 = __half22float2(*reinterpret_cast<__half2*>(&v.z));
    float2 f3 = __half22float2(*reinterpret_cast<__half2*>(&v.w));
    A.x += f0.x; A.y += f0.y; A.z += f1.x; A.w += f1.y;
    Cc.x += f2.x; Cc.y += f2.y; Cc.z += f3.x; Cc.w += f3.y;
}

__global__ __launch_bounds__(256)
void k_aggregate(const float* __restrict__ x,
                 const float* __restrict__ a_conv_b,
                 const float* __restrict__ c_conv_b)
{
    __shared__ float sab[CCH], scb[CCH];
    __shared__ float scsum[CCH];

    const int tid = threadIdx.x;
    if (tid < 128) { sab[tid] = a_conv_b[tid]; scb[tid] = c_conv_b[tid]; scsum[tid] = 0.f; }
    __syncthreads();

    const int lane = tid & 31;
    const int warp = tid >> 5;
    const int gw = blockIdx.x * (blockDim.x >> 5) + warp;
    const int nw = gridDim.x * (blockDim.x >> 5);

    float4 cs = make_float4(0.f, 0.f, 0.f, 0.f);
    uint2* atab = reinterpret_cast<uint2*>(g_atab);

    for (int node = gw; node < N_NODES; node += nw) {
        const float dv = g_dinv[node];
        float4 A  = make_float4(0.f, 0.f, 0.f, 0.f);
        float4 Cc = make_float4(0.f, 0.f, 0.f, 0.f);
        addh(A, Cc, g_feat_h[(size_t)node * 32 + lane]);     // self loop

        const int beg = g_off[node], end = g_off[node + 1];
        int j = beg;
        for (; j + 3 < end; j += 4) {
            int s0 = g_csr[j], s1 = g_csr[j + 1], s2 = g_csr[j + 2], s3 = g_csr[j + 3];
            uint4 v0 = g_feat_h[(size_t)s0 * 32 + lane];
            uint4 v1 = g_feat_h[(size_t)s1 * 32 + lane];
            uint4 v2 = g_feat_h[(size_t)s2 * 32 + lane];
            uint4 v3 = g_feat_h[(size_t)s3 * 32 + lane];
            addh(A, Cc, v0); addh(A, Cc, v1); addh(A, Cc, v2); addh(A, Cc, v3);
        }
        for (; j < end; j++) {
            uint4 v0 = g_feat_h[(size_t)g_csr[j] * 32 + lane];
            addh(A, Cc, v0);
        }

        float4 xv = reinterpret_cast<const float4*>(x)[(size_t)node * 32 + lane];
        int c0 = 4 * lane;
        float4 a;
        a.x = fmaxf(fmaf(A.x, dv, sab[c0 + 0]), 0.f) + xv.x;
        a.y = fmaxf(fmaf(A.y, dv, sab[c0 + 1]), 0.f) + xv.y;
        a.z = fmaxf(fmaf(A.z, dv, sab[c0 + 2]), 0.f) + xv.z;
        a.w = fmaxf(fmaf(A.w, dv, sab[c0 + 3]), 0.f) + xv.w;

        uint2 av;
        av.x = h2_as_u32(__floats2half2_rn(a.x, a.y));
        av.y = h2_as_u32(__floats2half2_rn(a.z, a.w));
        atab[(size_t)node * 32 + lane] = av;

        cs.x += fmaxf(fmaf(Cc.x, dv, scb[c0 + 0]), 0.f) + xv.x;
        cs.y += fmaxf(fmaf(Cc.y, dv, scb[c0 + 1]), 0.f) + xv.y;
        cs.z += fmaxf(fmaf(Cc.z, dv, scb[c0 + 2]), 0.f) + xv.z;
        cs.w += fmaxf(fmaf(Cc.w, dv, scb[c0 + 3]), 0.f) + xv.w;
    }

    int c0 = 4 * lane;
    atomicAdd(&scsum[c0 + 0], cs.x);
    atomicAdd(&scsum[c0 + 1], cs.y);
    atomicAdd(&scsum[c0 + 2], cs.z);
    atomicAdd(&scsum[c0 + 3], cs.w);
    __syncthreads();
    if (tid < CCH) atomicAdd(&g_csum[tid], scsum[tid]);
}

// ---------------------------------------------------------------- actor MLP via mma.sync (+ critic head block)
#define MLP_LDA 136
#define MLP_LDH 40
#define OFF_A  0
#define OFF_H1 34816
#define OFF_H2 45056
#define OFF_W1 55296
#define OFF_W2 64000
#define OFF_W3 66560
#define OFF_B  67200
#define MLP_SMEM 67584

__device__ __forceinline__ float softplus_f(float v) {
    return fmaxf(v, 0.f) + log1pf(expf(-fabsf(v))) + 1e-20f;
}

__global__ __launch_bounds__(128)
void k_mlp(const float* __restrict__ b1, const float* __restrict__ b2,
           const float* __restrict__ b3,
           const float* __restrict__ cW1, const float* __restrict__ cb1,
           const float* __restrict__ cW2, const float* __restrict__ cb2,
           const float* __restrict__ cW3, const float* __restrict__ cb3,
           float* __restrict__ out)
{
    // last block: critic value head (one warp), self-cleans g_csum
    if (blockIdx.x == GEMM_BX) {
        const int lane = threadIdx.x;
        if (lane >= 32) return;
        float c0 = g_csum[lane], c1 = g_csum[lane + 32],
              c2 = g_csum[lane + 64], c3 = g_csum[lane + 96];
        g_csum[lane] = 0.f; g_csum[lane + 32] = 0.f;
        g_csum[lane + 64] = 0.f; g_csum[lane + 96] = 0.f;
        float h1 = cb1[lane];
#pragma unroll
        for (int r = 0; r < 32; r++)
            h1 = fmaf(__shfl_sync(FULLM, c0, r), cW1[(r      ) * 32 + lane], h1);
#pragma unroll
        for (int r = 0; r < 32; r++)
            h1 = fmaf(__shfl_sync(FULLM, c1, r), cW1[(r + 32 ) * 32 + lane], h1);
#pragma unroll
        for (int r = 0; r < 32; r++)
            h1 = fmaf(__shfl_sync(FULLM, c2, r), cW1[(r + 64 ) * 32 + lane], h1);
#pragma unroll
        for (int r = 0; r < 32; r++)
            h1 = fmaf(__shfl_sync(FULLM, c3, r), cW1[(r + 96 ) * 32 + lane], h1);
        h1 = fmaxf(h1, 0.f);
        float h2 = cb2[lane];
#pragma unroll
        for (int r = 0; r < 32; r++)
            h2 = fmaf(__shfl_sync(FULLM, h1, r), cW2[r * 32 + lane], h2);
        h2 = fmaxf(h2, 0.f);
        float p = h2 * cW3[lane];
#pragma unroll
        for (int off = 16; off > 0; off >>= 1)
            p += __shfl_xor_sync(FULLM, p, off);
        if (lane == 0) out[(size_t)4 * N_NODES] = p + cb3[0];
        return;
    }

    extern __shared__ char sm[];
    const int tid = threadIdx.x;
    const int w = tid >> 5, lane = tid & 31;
    const int lq = lane >> 2, lr = lane & 3;
    const int bm = blockIdx.x * 128;

    float* fb1 = reinterpret_cast<float*>(sm + OFF_B);
    float* fb2 = fb1 + 32;
    float* fb3 = fb2 + 32;

    for (int g = tid; g < 32 * 64; g += 128) {
        int n = g >> 6, k2 = g & 63;
        *reinterpret_cast<uint32_t*>(sm + OFF_W1 + n * (MLP_LDA * 2) + k2 * 4) =
            reinterpret_cast<const uint32_t*>(g_w1t)[n * 64 + k2];
    }
    for (int g = tid; g < 32 * 16; g += 128) {
        int n = g >> 4, k2 = g & 15;
        *reinterpret_cast<uint32_t*>(sm + OFF_W2 + n * (MLP_LDH * 2) + k2 * 4) =
            reinterpret_cast<const uint32_t*>(g_w2t)[n * 16 + k2];
    }
    if (tid < 128) {
        int n = tid >> 4, k2 = tid & 15;
        *reinterpret_cast<uint32_t*>(sm + OFF_W3 + n * (MLP_LDH * 2) + k2 * 4) =
            reinterpret_cast<const uint32_t*>(g_w3t)[n * 16 + k2];
    }
    if (tid < 32) { fb1[tid] = b1[tid]; fb2[tid] = b2[tid]; }
    if (tid < 4)  { fb3[tid] = b3[tid]; }
    for (int g = tid; g < 128 * 16; g += 128) {
        int row = g >> 4, q = g & 15;
        uint4 v = make_uint4(0u, 0u, 0u, 0u);
        if (bm + row < N_NODES) v = g_atab[(size_t)(bm + row) * 16 + q];
        *reinterpret_cast<uint4*>(sm + OFF_A + row * (MLP_LDA * 2) + q * 16) = v;
    }
    __syncthreads();

    float acc1[2][4][4];
#pragma unroll
    for (int i = 0; i < 2; i++)
#pragma unroll
        for (int j = 0; j < 4; j++)
#pragma unroll
            for (int q = 0; q < 4; q++) acc1[i][j][q] = 0.f;

#pragma unroll
    for (int ks = 0; ks < 8; ks++) {
        uint32_t a[2][4];
#pragma unroll
        for (int ma = 0; ma < 2; ma++) {
            int row = w * 32 + ma * 16 + lq;
            uint32_t o = OFF_A + row * (MLP_LDA * 2) + (ks * 16 + lr * 2) * 2;
            a[ma][0] = *reinterpret_cast<uint32_t*>(sm + o);
            a[ma][1] = *reinterpret_cast<uint32_t*>(sm + o + 8 * (MLP_LDA * 2));
            a[ma][2] = *reinterpret_cast<uint32_t*>(sm + o + 16);
            a[ma][3] = *reinterpret_cast<uint32_t*>(sm + o + 8 * (MLP_LDA * 2) + 16);
        }
#pragma unroll
        for (int nb = 0; nb < 4; nb++) {
            int n = nb * 8 + lq;
            uint32_t o = OFF_W1 + n * (MLP_LDA * 2) + (ks * 16 + lr * 2) * 2;
            uint32_t b[2];
            b[0] = *reinterpret_cast<uint32_t*>(sm + o);
            b[1] = *reinterpret_cast<uint32_t*>(sm + o + 16);
#pragma unroll
            for (int ma = 0; ma < 2; ma++) mma16816h(acc1[ma][nb], a[ma], b);
        }
    }
#pragma unroll
    for (int ma = 0; ma < 2; ma++) {
        int row = w * 32 + ma * 16 + lq;
#pragma unroll
        for (int nb = 0; nb < 4; nb++) {
            int col = nb * 8 + lr * 2;
            float v0 = fmaxf(acc1[ma][nb][0] + fb1[col], 0.f);
            float v1 = fmaxf(acc1[ma][nb][1] + fb1[col + 1], 0.f);
            float v2 = fmaxf(acc1[ma][nb][2] + fb1[col], 0.f);
            float v3 = fmaxf(acc1[ma][nb][3] + fb1[col + 1], 0.f);
            *reinterpret_cast<uint32_t*>(sm + OFF_H1 + row * (MLP_LDH * 2) + col * 2) =
                h2_as_u32(__floats2half2_rn(v0, v1));
            *reinterpret_cast<uint32_t*>(sm + OFF_H1 + (row + 8) * (MLP_LDH * 2) + col * 2) =
                h2_as_u32(__floats2half2_rn(v2, v3));
        }
    }
    __syncwarp();

    float acc2[2][4][4];
#pragma unroll
    for (int i = 0; i < 2; i++)
#pragma unroll
        for (int j = 0; j < 4; j++)
#pragma unroll
            for (int q = 0; q < 4; q++) acc2[i][j][q] = 0.f;
#pragma unroll
    for (int ks = 0; ks < 2; ks++) {
        uint32_t a[2][4];
#pragma unroll
        for (int ma = 0; ma < 2; ma++) {
            int row = w * 32 + ma * 16 + lq;
            uint32_t o = OFF_H1 + row * (MLP_LDH * 2) + (ks * 16 + lr * 2) * 2;
            a[ma][0] = *reinterpret_cast<uint32_t*>(sm + o);
            a[ma][1] = *reinterpret_cast<uint32_t*>(sm + o + 8 * (MLP_LDH * 2));
            a[ma][2] = *reinterpret_cast<uint32_t*>(sm + o + 16);
            a[ma][3] = *reinterpret_cast<uint32_t*>(sm + o + 8 * (MLP_LDH * 2) + 16);
        }
#pragma unroll
        for (int nb = 0; nb < 4; nb++) {
            int n = nb * 8 + lq;
            uint32_t o = OFF_W2 + n * (MLP_LDH * 2) + (ks * 16 + lr * 2) * 2;
            uint32_t b[2];
            b[0] = *reinterpret_cast<uint32_t*>(sm + o);
            b[1] = *reinterpret_cast<uint32_t*>(sm + o + 16);
#pragma unroll
            for (int ma = 0; ma < 2; ma++) mma16816h(acc2[ma][nb], a[ma], b);
        }
    }
#pragma unroll
    for (int ma = 0; ma < 2; ma++) {
        int row = w * 32 + ma * 16 + lq;
#pragma unroll
        for (int nb = 0; nb < 4; nb++) {
            int col = nb * 8 + lr * 2;
            float v0 = fmaxf(acc2[ma][nb][0] + fb2[col], 0.f);
            float v1 = fmaxf(acc2[ma][nb][1] + fb2[col + 1], 0.f);
            float v2 = fmaxf(acc2[ma][nb][2] + fb2[col], 0.f);
            float v3 = fmaxf(acc2[ma][nb][3] + fb2[col + 1], 0.f);
            *reinterpret_cast<uint32_t*>(sm + OFF_H2 + row * (MLP_LDH * 2) + col * 2) =
                h2_as_u32(__floats2half2_rn(v0, v1));
            *reinterpret_cast<uint32_t*>(sm + OFF_H2 + (row + 8) * (MLP_LDH * 2) + col * 2) =
                h2_as_u32(__floats2half2_rn(v2, v3));
        }
    }
    __syncwarp();

    float acc3[2][4];
#pragma unroll
    for (int i = 0; i < 2; i++)
#pragma unroll
        for (int q = 0; q < 4; q++) acc3[i][q] = 0.f;
#pragma unroll
    for (int ks = 0; ks < 2; ks++) {
        uint32_t a[2][4];
#pragma unroll
        for (int ma = 0; ma < 2; ma++) {
            int row = w * 32 + ma * 16 + lq;
            uint32_t o = OFF_H2 + row * (MLP_LDH * 2) + (ks * 16 + lr * 2) * 2;
            a[ma][0] = *reinterpret_cast<uint32_t*>(sm + o);
            a[ma][1] = *reinterpret_cast<uint32_t*>(sm + o + 8 * (MLP_LDH * 2));
            a[ma][2] = *reinterpret_cast<uint32_t*>(sm + o + 16);
            a[ma][3] = *reinterpret_cast<uint32_t*>(sm + o + 8 * (MLP_LDH * 2) + 16);
        }
        int n = lq;
        uint32_t o = OFF_W3 + n * (MLP_LDH * 2) + (ks * 16 + lr * 2) * 2;
        uint32_t b[2];
        b[0] = *reinterpret_cast<uint32_t*>(sm + o);
        b[1] = *reinterpret_cast<uint32_t*>(sm + o + 16);
#pragma unroll
        for (int ma = 0; ma < 2; ma++) mma16816h(acc3[ma], a[ma], b);
    }
    if (lr < 2) {
        int ca = 2 * lr, cb = 2 * lr + 1;
#pragma unroll
        for (int ma = 0; ma < 2; ma++) {
            int r0 = bm + w * 32 + ma * 16 + lq;
            int r1 = r0 + 8;
            if (r0 < N_NODES) {
                float s0 = softplus_f(acc3[ma][0] + fb3[ca]);
                float s1 = softplus_f(acc3[ma][1] + fb3[cb]);
                if (ca == 0) out[r0] = s0; else out[N_NODES + (size_t)r0 * 3 + ca - 1] = s0;
                out[N_NODES + (size_t)r0 * 3 + cb - 1] = s1;
            }
            if (r1 < N_NODES) {
                float s2 = softplus_f(acc3[ma][2] + fb3[ca]);
                float s3 = softplus_f(acc3[ma][3] + fb3[cb]);
                if (ca == 0) out[r1] = s2; else out[N_NODES + (size_t)r1 * 3 + ca - 1] = s2;
                out[N_NODES + (size_t)r1 * 3 + cb - 1] = s3;
            }
        }
    }
}

// ---------------------------------------------------------------- launch
extern "C" void kernel_launch(void* const* d_in, const int* in_sizes, int n_in,
                              void* d_out, int out_size)
{
    const float* x    = (const float*)d_in[0];
    const int*   ei   = (const int*)  d_in[1];
    const float* aW   = (const float*)d_in[2];
    const float* ab   = (const float*)d_in[3];
    const float* aW1  = (const float*)d_in[4];
    const float* ab1  = (const float*)d_in[5];
    const float* aW2  = (const float*)d_in[6];
    const float* ab2  = (const float*)d_in[7];
    const float* aW3  = (const float*)d_in[8];
    const float* ab3  = (const float*)d_in[9];
    const float* cW   = (const float*)d_in[10];
    const float* cb   = (const float*)d_in[11];
    const float* cW1  = (const float*)d_in[12];
    const float* cb1  = (const float*)d_in[13];
    const float* cW2  = (const float*)d_in[14];
    const float* cb2  = (const float*)d_in[15];
    const float* cW3  = (const float*)d_in[16];
    const float* cb3  = (const float*)d_in[17];
    float* out = (float*)d_out;

    const int* src = ei;
    const int* dst = ei + N_EDGES;

    cudaFuncSetAttribute((const void*)k_gemm_fill,
                         cudaFuncAttributeMaxDynamicSharedMemorySize, SM_TOTAL_MMA);
    cudaFuncSetAttribute((const void*)k_mlp,
                         cudaFuncAttributeMaxDynamicSharedMemorySize, MLP_SMEM);

    k_degree_prep<<<FILL_B + WPREP_B + MLPP_B, 256>>>(dst, aW, cW, aW1, aW2, aW3);
    k_scan1      <<<SCAN_G, SCAN_B>>>();
    k_scan3      <<<SCAN_G, SCAN_B>>>();

    k_gemm_fill<<<2 * GEMM_BX + FILL_B, 256, SM_TOTAL_MMA>>>(x, src, dst);

    k_aggregate<<<2048, 256>>>(x, ab, cb);

    k_mlp<<<GEMM_BX + 1, 128, MLP_SMEM>>>(ab1, ab2, ab3,
                                          cW1, cb1, cW2, cb2, cW3, cb3, out);
}

// round 17
// speedup vs baseline: 1.3834x; 1.1013x over previous
#include <cuda_runtime.h>
#include <cuda_fp16.h>
#include <stdint.h>
#include <math.h>

#define N_NODES 100000
#define N_EDGES 1600000
#define CCH 128
#define FULLM 0xffffffffu
#define SCAN_B 1024
#define SCAN_G ((N_NODES + SCAN_B - 1) / SCAN_B)   // 98
#define GEMM_BX ((N_NODES + 127) / 128)            // 782
#define FILL_B  ((N_EDGES + 255) / 256)            // 6250
#define WPREP_B 128
#define MLPP_B  21

// ---------------- device scratch (zero-initialized at load; kernels self-clean) ----------------
__device__ uint4 g_feat_h[(size_t)N_NODES * 32];
__device__ uint4 g_atab[(size_t)N_NODES * 16];
__device__ int   g_deg [N_NODES];
__device__ float g_dinv[N_NODES];
__device__ int   g_off [N_NODES + 1];
__device__ int   g_cur [N_NODES];
__device__ int   g_csr [N_EDGES];
__device__ int   g_bsum[SCAN_G];
__device__ float g_csum[CCH];
__device__ unsigned short g_wt[2 * CCH * CCH];     // W^T fp16: [half][n][k]
__device__ unsigned short g_w1t[32 * 128];
__device__ unsigned short g_w2t[32 * 32];
__device__ unsigned short g_w3t[8 * 32];

__device__ __forceinline__ unsigned int h2_as_u32(__half2 h) {
    return *reinterpret_cast<unsigned int*>(&h);
}
__device__ __forceinline__ uint32_t smem_u32(const void* p) {
    uint32_t a;
    asm("{ .reg .u64 t; cvta.to.shared.u64 t, %1; cvt.u32.u64 %0, t; }" : "=r"(a) : "l"(p));
    return a;
}

// ---------------------------------------------------------------- degree + weight preps (fused)
__global__ void k_degree_prep(const int* __restrict__ dst,
                              const float* __restrict__ Wa, const float* __restrict__ Wc,
                              const float* __restrict__ W1, const float* __restrict__ W2,
                              const float* __restrict__ W3) {
    int b = blockIdx.x;
    if (b < FILL_B) {
        int i = b * 256 + threadIdx.x;
        if (i < N_EDGES) atomicAdd(&g_deg[dst[i]], 1);
        return;
    }
    b -= FILL_B;
    if (b < WPREP_B) {
        int idx = b * 256 + threadIdx.x;          // < 32768
        int h = idx >> 14;
        int rem = idx & 16383;
        int n = rem >> 7, k = rem & 127;
        const float* W = h ? Wc : Wa;
        __half hv = __float2half(W[k * CCH + n]);
        g_wt[idx] = *reinterpret_cast<unsigned short*>(&hv);
        return;
    }
    b -= WPREP_B;
    int idx = b * 256 + threadIdx.x;
    if (idx < 32 * 128) {
        int n = idx >> 7, k = idx & 127;
        __half h = __float2half(W1[k * 32 + n]);
        g_w1t[idx] = *reinterpret_cast<unsigned short*>(&h);
    } else if (idx < 32 * 128 + 32 * 32) {
        int j = idx - 32 * 128;
        int n = j >> 5, k = j & 31;
        __half h = __float2half(W2[k * 32 + n]);
        g_w2t[j] = *reinterpret_cast<unsigned short*>(&h);
    } else if (idx < 32 * 128 + 32 * 32 + 8 * 32) {
        int j = idx - 32 * 128 - 32 * 32;
        int n = j >> 5, k = j & 31;
        float v = (n < 4) ? W3[k * 4 + n] : 0.f;
        __half h = __float2half(v);
        g_w3t[j] = *reinterpret_cast<unsigned short*>(&h);
    }
}

// ---------------- scans (merged 2-phase; self-cleaning) ----------------
__device__ __forceinline__ int block_excl_scan(int v, int lane, int wid, int* warp_sums, int nwarp) {
    int inc = v;
#pragma unroll
    for (int o = 1; o < 32; o <<= 1) {
        int u = __shfl_up_sync(FULLM, inc, o);
        if (lane >= o) inc += u;
    }
    if (lane == 31) warp_sums[wid] = inc;
    __syncthreads();
    if (wid == 0) {
        int w = (lane < nwarp) ? warp_sums[lane] : 0;
#pragma unroll
        for (int o = 1; o < 32; o <<= 1) {
            int u = __shfl_up_sync(FULLM, w, o);
            if (lane >= o) w += u;
        }
        warp_sums[lane] = w;
    }
    __syncthreads();
    return (inc - v) + (wid ? warp_sums[wid - 1] : 0);
}
__global__ void k_scan1() {
    __shared__ int warp_sums[32];
    int i = blockIdx.x * SCAN_B + threadIdx.x;
    int d = 0;
    if (i < N_NODES) {
        d = g_deg[i];
        g_deg[i] = 0;                              // self-clean for graph replay
        g_dinv[i] = rsqrtf((float)(d + 1));
    }
    int ex = block_excl_scan(d, threadIdx.x & 31, threadIdx.x >> 5, warp_sums, SCAN_B / 32);
    if (i < N_NODES) g_off[i] = ex;
    if (threadIdx.x == SCAN_B - 1) g_bsum[blockIdx.x] = ex + d;
}
__global__ void k_scan3() {
    __shared__ int sbase;
    const int lane = threadIdx.x & 31;
    if (threadIdx.x < 32) {
        int s = 0;
        for (int t = lane; t < blockIdx.x; t += 32) s += g_bsum[t];
#pragma unroll
        for (int o = 16; o > 0; o >>= 1) s += __shfl_xor_sync(FULLM, s, o);
        if (lane == 0) sbase = s;
    }
    __syncthreads();
    int i = blockIdx.x * SCAN_B + threadIdx.x;
    if (i < N_NODES) {
        int o = g_off[i] + sbase;
        g_off[i] = o;
        g_cur[i] = o;
    }
    if (i == 0) g_off[N_NODES] = N_EDGES;
}

// ---------------------------------------------------------------- fp16 mma GEMM (ldmatrix) + CSR fill
// Whole K=128 resident in fp16: A 128x128, B 128x128, stride 136 halves.
#define LDH 136
#define SM_A 0                            // 128*136*2 = 34816
#define SM_B 34816
#define SM_TOTAL_MMA (2 * 34816)          // 69632 B

__device__ __forceinline__ void mma16816h(float c[4], const uint32_t a[4], const uint32_t b0, const uint32_t b1) {
    asm volatile("mma.sync.aligned.m16n8k16.row.col.f32.f16.f16.f32 "
                 "{%0,%1,%2,%3}, {%4,%5,%6,%7}, {%8,%9}, {%0,%1,%2,%3};\n"
                 : "+f"(c[0]), "+f"(c[1]), "+f"(c[2]), "+f"(c[3])
                 : "r"(a[0]), "r"(a[1]), "r"(a[2]), "r"(a[3]), "r"(b0), "r"(b1));
}
__device__ __forceinline__ void mma16816ha(float c[4], const uint32_t a[4], const uint32_t b[2]) {
    mma16816h(c, a, b[0], b[1]);
}
#define LDSM_X4(r0, r1, r2, r3, addr) \
    asm volatile("ldmatrix.sync.aligned.m8n8.x4.shared.b16 {%0,%1,%2,%3}, [%4];" \
                 : "=r"(r0), "=r"(r1), "=r"(r2), "=r"(r3) : "r"(addr))

__global__ __launch_bounds__(256)
void k_gemm_fill(const float* __restrict__ x,
                 const int* __restrict__ src,
                 const int* __restrict__ dst)
{
    if (blockIdx.x >= 2 * GEMM_BX) {
        int e = (blockIdx.x - 2 * GEMM_BX) * 256 + threadIdx.x;
        if (e < N_EDGES) {
            int d = dst[e];
            int p = atomicAdd(&g_cur[d], 1);
            g_csr[p] = src[e];
        }
        return;
    }

    extern __shared__ char smem[];
    unsigned short* smA = reinterpret_cast<unsigned short*>(smem + SM_A);
    unsigned short* smB = reinterpret_cast<unsigned short*>(smem + SM_B);
    const int tid  = threadIdx.x;
    const int wid  = tid >> 5, lane = tid & 31;
    const int half = (blockIdx.x >= GEMM_BX) ? 1 : 0;
    const int bm   = (blockIdx.x - half * GEMM_BX) * 128;
    const int wm   = wid & 3;        // 32-row group
    const int wn   = wid >> 2;       // 64-col group

    // ---- stage A (x -> fp16) : 128 rows x 128 k ----
    for (int g = tid; g < 2048; g += 256) {
        int row = g >> 4, c8 = (g & 15) * 8;
        float4 v0 = make_float4(0.f, 0.f, 0.f, 0.f), v1 = v0;
        if (bm + row < N_NODES) {
            const float4* xp = reinterpret_cast<const float4*>(
                &x[(size_t)(bm + row) * CCH + c8]);
            v0 = xp[0]; v1 = xp[1];
        }
        uint4 u;
        u.x = h2_as_u32(__floats2half2_rn(v0.x, v0.y));
        u.y = h2_as_u32(__floats2half2_rn(v0.z, v0.w));
        u.z = h2_as_u32(__floats2half2_rn(v1.x, v1.y));
        u.w = h2_as_u32(__floats2half2_rn(v1.z, v1.w));
        *reinterpret_cast<uint4*>(&smA[row * LDH + c8]) = u;
    }
    // ---- stage B (precomputed fp16 W^T) ----
    for (int g = tid; g < 2048; g += 256) {
        int n = g >> 4, c8 = (g & 15) * 8;
        *reinterpret_cast<uint4*>(&smB[n * LDH + c8]) =
            *reinterpret_cast<const uint4*>(&g_wt[((size_t)(half * 128 + n)) * 128 + c8]);
    }
    __syncthreads();

    float acc[2][8][4];
#pragma unroll
    for (int i = 0; i < 2; i++)
#pragma unroll
        for (int j = 0; j < 8; j++)
#pragma unroll
            for (int q = 0; q < 4; q++) acc[i][j][q] = 0.f;

    // ldmatrix lane mapping
    const int lm  = lane >> 3;        // matrix index 0..3
    const int l8  = lane & 7;
    const uint32_t sb = smem_u32(smem);
    // A: m0=(rlo,klo) m1=(rhi,klo) m2=(rlo,khi) m3=(rhi,khi)
    uint32_t aAddr[2];
#pragma unroll
    for (int ma = 0; ma < 2; ma++) {
        int row = wm * 32 + ma * 16 + (lm & 1) * 8 + l8;
        int kof = (lm >> 1) * 8;
        aAddr[ma] = sb + SM_A + (uint32_t)(row * LDH + kof) * 2;
    }
    // B: m0=(nlo,klo) m1=(nlo,khi) m2=(nhi,klo) m3=(nhi,khi)
    uint32_t bAddr[4];
#pragma unroll
    for (int nbp = 0; nbp < 4; nbp++) {
        int n = wn * 64 + nbp * 16 + (lm >> 1) * 8 + l8;
        int kof = (lm & 1) * 8;
        bAddr[nbp] = sb + SM_B + (uint32_t)(n * LDH + kof) * 2;
    }

#pragma unroll
    for (int ks = 0; ks < 8; ks++) {
        const uint32_t kb = ks * 32;          // 16 halves = 32 bytes
        uint32_t a[2][4];
        LDSM_X4(a[0][0], a[0][1], a[0][2], a[0][3], aAddr[0] + kb);
        LDSM_X4(a[1][0], a[1][1], a[1][2], a[1][3], aAddr[1] + kb);
#pragma unroll
        for (int nbp = 0; nbp < 4; nbp++) {
            uint32_t b0, b1, b2, b3;
            LDSM_X4(b0, b1, b2, b3, bAddr[nbp] + kb);
            mma16816h(acc[0][2 * nbp],     a[0], b0, b1);
            mma16816h(acc[1][2 * nbp],     a[1], b0, b1);
            mma16816h(acc[0][2 * nbp + 1], a[0], b2, b3);
            mma16816h(acc[1][2 * nbp + 1], a[1], b2, b3);
        }
    }

    // ---- epilogue: same fragment layout as before ----
    const int lq = lane >> 2, lr = lane & 3;
    unsigned char* fb = reinterpret_cast<unsigned char*>(g_feat_h);
#pragma unroll
    for (int ma = 0; ma < 2; ma++) {
        int row0 = bm + wm * 32 + ma * 16 + lq;
        int row1 = row0 + 8;
        float dv0 = (row0 < N_NODES) ? g_dinv[row0] : 0.f;
        float dv1 = (row1 < N_NODES) ? g_dinv[row1] : 0.f;
#pragma unroll
        for (int nb = 0; nb < 8; nb++) {
            int cpair = wn * 32 + nb * 4 + lr;
            uint32_t cb = (uint32_t)(cpair >> 1) * 16 + (uint32_t)half * 8 + (cpair & 1) * 4;
            if (row0 < N_NODES) {
                *reinterpret_cast<uint32_t*>(fb + (size_t)row0 * 512 + cb) =
                    h2_as_u32(__floats2half2_rn(acc[ma][nb][0] * dv0, acc[ma][nb][1] * dv0));
            }
            if (row1 < N_NODES) {
                *reinterpret_cast<uint32_t*>(fb + (size_t)row1 * 512 + cb) =
                    h2_as_u32(__floats2half2_rn(acc[ma][nb][2] * dv1, acc[ma][nb][3] * dv1));
            }
        }
    }
}

// ---------------------------------------------------------------- gather + conv epilogue
__device__ __forceinline__ void addh(float4& A, float4& Cc, uint4 v) {
    float2 f0 = __half22float2(*reinterpret_cast<__half2*>(&v.x));
    float2 f1 = __half22float2(*reinterpret_cast<__half2*>(&v.y));
    float2 f2 = __half22float2(*reinterpret_cast<__half2*>(&v.z));
    float2 f3 = __half22float2(*reinterpret_cast<__half2*>(&v.w));
    A.x += f0.x; A.y += f0.y; A.z += f1.x; A.w += f1.y;
    Cc.x += f2.x; Cc.y += f2.y; Cc.z += f3.x; Cc.w += f3.y;
}

__global__ __launch_bounds__(256)
void k_aggregate(const float* __restrict__ x,
                 const float* __restrict__ a_conv_b,
                 const float* __restrict__ c_conv_b)
{
    __shared__ float sab[CCH], scb[CCH];
    __shared__ float scsum[CCH];

    const int tid = threadIdx.x;
    if (tid < 128) { sab[tid] = a_conv_b[tid]; scb[tid] = c_conv_b[tid]; scsum[tid] = 0.f; }
    __syncthreads();

    const int lane = tid & 31;
    const int warp = tid >> 5;
    const int gw = blockIdx.x * (blockDim.x >> 5) + warp;
    const int nw = gridDim.x * (blockDim.x >> 5);

    float4 cs = make_float4(0.f, 0.f, 0.f, 0.f);
    uint2* atab = reinterpret_cast<uint2*>(g_atab);

    for (int node = gw; node < N_NODES; node += nw) {
        const float dv = g_dinv[node];
        float4 A  = make_float4(0.f, 0.f, 0.f, 0.f);
        float4 Cc = make_float4(0.f, 0.f, 0.f, 0.f);
        addh(A, Cc, g_feat_h[(size_t)node * 32 + lane]);     // self loop

        const int beg = g_off[node], end = g_off[node + 1];
        int j = beg;
        for (; j + 3 < end; j += 4) {
            int s0 = g_csr[j], s1 = g_csr[j + 1], s2 = g_csr[j + 2], s3 = g_csr[j + 3];
            uint4 v0 = g_feat_h[(size_t)s0 * 32 + lane];
            uint4 v1 = g_feat_h[(size_t)s1 * 32 + lane];
            uint4 v2 = g_feat_h[(size_t)s2 * 32 + lane];
            uint4 v3 = g_feat_h[(size_t)s3 * 32 + lane];
            addh(A, Cc, v0); addh(A, Cc, v1); addh(A, Cc, v2); addh(A, Cc, v3);
        }
        for (; j < end; j++) {
            uint4 v0 = g_feat_h[(size_t)g_csr[j] * 32 + lane];
            addh(A, Cc, v0);
        }

        float4 xv = reinterpret_cast<const float4*>(x)[(size_t)node * 32 + lane];
        int c0 = 4 * lane;
        float4 a;
        a.x = fmaxf(fmaf(A.x, dv, sab[c0 + 0]), 0.f) + xv.x;
        a.y = fmaxf(fmaf(A.y, dv, sab[c0 + 1]), 0.f) + xv.y;
        a.z = fmaxf(fmaf(A.z, dv, sab[c0 + 2]), 0.f) + xv.z;
        a.w = fmaxf(fmaf(A.w, dv, sab[c0 + 3]), 0.f) + xv.w;

        uint2 av;
        av.x = h2_as_u32(__floats2half2_rn(a.x, a.y));
        av.y = h2_as_u32(__floats2half2_rn(a.z, a.w));
        atab[(size_t)node * 32 + lane] = av;

        cs.x += fmaxf(fmaf(Cc.x, dv, scb[c0 + 0]), 0.f) + xv.x;
        cs.y += fmaxf(fmaf(Cc.y, dv, scb[c0 + 1]), 0.f) + xv.y;
        cs.z += fmaxf(fmaf(Cc.z, dv, scb[c0 + 2]), 0.f) + xv.z;
        cs.w += fmaxf(fmaf(Cc.w, dv, scb[c0 + 3]), 0.f) + xv.w;
    }

    int c0 = 4 * lane;
    atomicAdd(&scsum[c0 + 0], cs.x);
    atomicAdd(&scsum[c0 + 1], cs.y);
    atomicAdd(&scsum[c0 + 2], cs.z);
    atomicAdd(&scsum[c0 + 3], cs.w);
    __syncthreads();
    if (tid < CCH) atomicAdd(&g_csum[tid], scsum[tid]);
}

// ---------------------------------------------------------------- actor MLP via mma.sync (+ critic head block)
#define MLP_LDA 136
#define MLP_LDH 40
#define OFF_A  0
#define OFF_H1 34816
#define OFF_H2 45056
#define OFF_W1 55296
#define OFF_W2 64000
#define OFF_W3 66560
#define OFF_B  67200
#define MLP_SMEM 67584

__device__ __forceinline__ float softplus_f(float v) {
    return fmaxf(v, 0.f) + log1pf(expf(-fabsf(v))) + 1e-20f;
}

__global__ __launch_bounds__(128)
void k_mlp(const float* __restrict__ b1, const float* __restrict__ b2,
           const float* __restrict__ b3,
           const float* __restrict__ cW1, const float* __restrict__ cb1,
           const float* __restrict__ cW2, const float* __restrict__ cb2,
           const float* __restrict__ cW3, const float* __restrict__ cb3,
           float* __restrict__ out)
{
    // last block: critic value head (one warp), self-cleans g_csum
    if (blockIdx.x == GEMM_BX) {
        const int lane = threadIdx.x;
        if (lane >= 32) return;
        float c0 = g_csum[lane], c1 = g_csum[lane + 32],
              c2 = g_csum[lane + 64], c3 = g_csum[lane + 96];
        g_csum[lane] = 0.f; g_csum[lane + 32] = 0.f;
        g_csum[lane + 64] = 0.f; g_csum[lane + 96] = 0.f;
        float h1 = cb1[lane];
#pragma unroll
        for (int r = 0; r < 32; r++)
            h1 = fmaf(__shfl_sync(FULLM, c0, r), cW1[(r      ) * 32 + lane], h1);
#pragma unroll
        for (int r = 0; r < 32; r++)
            h1 = fmaf(__shfl_sync(FULLM, c1, r), cW1[(r + 32 ) * 32 + lane], h1);
#pragma unroll
        for (int r = 0; r < 32; r++)
            h1 = fmaf(__shfl_sync(FULLM, c2, r), cW1[(r + 64 ) * 32 + lane], h1);
#pragma unroll
        for (int r = 0; r < 32; r++)
            h1 = fmaf(__shfl_sync(FULLM, c3, r), cW1[(r + 96 ) * 32 + lane], h1);
        h1 = fmaxf(h1, 0.f);
        float h2 = cb2[lane];
#pragma unroll
        for (int r = 0; r < 32; r++)
            h2 = fmaf(__shfl_sync(FULLM, h1, r), cW2[r * 32 + lane], h2);
        h2 = fmaxf(h2, 0.f);
        float p = h2 * cW3[lane];
#pragma unroll
        for (int off = 16; off > 0; off >>= 1)
            p += __shfl_xor_sync(FULLM, p, off);
        if (lane == 0) out[(size_t)4 * N_NODES] = p + cb3[0];
        return;
    }

    extern __shared__ char sm[];
    const int tid = threadIdx.x;
    const int w = tid >> 5, lane = tid & 31;
    const int lq = lane >> 2, lr = lane & 3;
    const int bm = blockIdx.x * 128;

    float* fb1 = reinterpret_cast<float*>(sm + OFF_B);
    float* fb2 = fb1 + 32;
    float* fb3 = fb2 + 32;

    for (int g = tid; g < 32 * 64; g += 128) {
        int n = g >> 6, k2 = g & 63;
        *reinterpret_cast<uint32_t*>(sm + OFF_W1 + n * (MLP_LDA * 2) + k2 * 4) =
            reinterpret_cast<const uint32_t*>(g_w1t)[n * 64 + k2];
    }
    for (int g = tid; g < 32 * 16; g += 128) {
        int n = g >> 4, k2 = g & 15;
        *reinterpret_cast<uint32_t*>(sm + OFF_W2 + n * (MLP_LDH * 2) + k2 * 4) =
            reinterpret_cast<const uint32_t*>(g_w2t)[n * 16 + k2];
    }
    if (tid < 128) {
        int n = tid >> 4, k2 = tid & 15;
        *reinterpret_cast<uint32_t*>(sm + OFF_W3 + n * (MLP_LDH * 2) + k2 * 4) =
            reinterpret_cast<const uint32_t*>(g_w3t)[n * 16 + k2];
    }
    if (tid < 32) { fb1[tid] = b1[tid]; fb2[tid] = b2[tid]; }
    if (tid < 4)  { fb3[tid] = b3[tid]; }
    for (int g = tid; g < 128 * 16; g += 128) {
        int row = g >> 4, q = g & 15;
        uint4 v = make_uint4(0u, 0u, 0u, 0u);
        if (bm + row < N_NODES) v = g_atab[(size_t)(bm + row) * 16 + q];
        *reinterpret_cast<uint4*>(sm + OFF_A + row * (MLP_LDA * 2) + q * 16) = v;
    }
    __syncthreads();

    float acc1[2][4][4];
#pragma unroll
    for (int i = 0; i < 2; i++)
#pragma unroll
        for (int j = 0; j < 4; j++)
#pragma unroll
            for (int q = 0; q < 4; q++) acc1[i][j][q] = 0.f;

#pragma unroll
    for (int ks = 0; ks < 8; ks++) {
        uint32_t a[2][4];
#pragma unroll
        for (int ma = 0; ma < 2; ma++) {
            int row = w * 32 + ma * 16 + lq;
            uint32_t o = OFF_A + row * (MLP_LDA * 2) + (ks * 16 + lr * 2) * 2;
            a[ma][0] = *reinterpret_cast<uint32_t*>(sm + o);
            a[ma][1] = *reinterpret_cast<uint32_t*>(sm + o + 8 * (MLP_LDA * 2));
            a[ma][2] = *reinterpret_cast<uint32_t*>(sm + o + 16);
            a[ma][3] = *reinterpret_cast<uint32_t*>(sm + o + 8 * (MLP_LDA * 2) + 16);
        }
#pragma unroll
        for (int nb = 0; nb < 4; nb++) {
            int n = nb * 8 + lq;
            uint32_t o = OFF_W1 + n * (MLP_LDA * 2) + (ks * 16 + lr * 2) * 2;
            uint32_t b[2];
            b[0] = *reinterpret_cast<uint32_t*>(sm + o);
            b[1] = *reinterpret_cast<uint32_t*>(sm + o + 16);
#pragma unroll
            for (int ma = 0; ma < 2; ma++) mma16816ha(acc1[ma][nb], a[ma], b);
        }
    }
#pragma unroll
    for (int ma = 0; ma < 2; ma++) {
        int row = w * 32 + ma * 16 + lq;
#pragma unroll
        for (int nb = 0; nb < 4; nb++) {
            int col = nb * 8 + lr * 2;
            float v0 = fmaxf(acc1[ma][nb][0] + fb1[col], 0.f);
            float v1 = fmaxf(acc1[ma][nb][1] + fb1[col + 1], 0.f);
            float v2 = fmaxf(acc1[ma][nb][2] + fb1[col], 0.f);
            float v3 = fmaxf(acc1[ma][nb][3] + fb1[col + 1], 0.f);
            *reinterpret_cast<uint32_t*>(sm + OFF_H1 + row * (MLP_LDH * 2) + col * 2) =
                h2_as_u32(__floats2half2_rn(v0, v1));
            *reinterpret_cast<uint32_t*>(sm + OFF_H1 + (row + 8) * (MLP_LDH * 2) + col * 2) =
                h2_as_u32(__floats2half2_rn(v2, v3));
        }
    }
    __syncwarp();

    float acc2[2][4][4];
#pragma unroll
    for (int i = 0; i < 2; i++)
#pragma unroll
        for (int j = 0; j < 4; j++)
#pragma unroll
            for (int q = 0; q < 4; q++) acc2[i][j][q] = 0.f;
#pragma unroll
    for (int ks = 0; ks < 2; ks++) {
        uint32_t a[2][4];
#pragma unroll
        for (int ma = 0; ma < 2; ma++) {
            int row = w * 32 + ma * 16 + lq;
            uint32_t o = OFF_H1 + row * (MLP_LDH * 2) + (ks * 16 + lr * 2) * 2;
            a[ma][0] = *reinterpret_cast<uint32_t*>(sm + o);
            a[ma][1] = *reinterpret_cast<uint32_t*>(sm + o + 8 * (MLP_LDH * 2));
            a[ma][2] = *reinterpret_cast<uint32_t*>(sm + o + 16);
            a[ma][3] = *reinterpret_cast<uint32_t*>(sm + o + 8 * (MLP_LDH * 2) + 16);
        }
#pragma unroll
        for (int nb = 0; nb < 4; nb++) {
            int n = nb * 8 + lq;
            uint32_t o = OFF_W2 + n * (MLP_LDH * 2) + (ks * 16 + lr * 2) * 2;
            uint32_t b[2];
            b[0] = *reinterpret_cast<uint32_t*>(sm + o);
            b[1] = *reinterpret_cast<uint32_t*>(sm + o + 16);
#pragma unroll
            for (int ma = 0; ma < 2; ma++) mma16816ha(acc2[ma][nb], a[ma], b);
        }
    }
#pragma unroll
    for (int ma = 0; ma < 2; ma++) {
        int row = w * 32 + ma * 16 + lq;
#pragma unroll
        for (int nb = 0; nb < 4; nb++) {
            int col = nb * 8 + lr * 2;
            float v0 = fmaxf(acc2[ma][nb][0] + fb2[col], 0.f);
            float v1 = fmaxf(acc2[ma][nb][1] + fb2[col + 1], 0.f);
            float v2 = fmaxf(acc2[ma][nb][2] + fb2[col], 0.f);
            float v3 = fmaxf(acc2[ma][nb][3] + fb2[col + 1], 0.f);
            *reinterpret_cast<uint32_t*>(sm + OFF_H2 + row * (MLP_LDH * 2) + col * 2) =
                h2_as_u32(__floats2half2_rn(v0, v1));
            *reinterpret_cast<uint32_t*>(sm + OFF_H2 + (row + 8) * (MLP_LDH * 2) + col * 2) =
                h2_as_u32(__floats2half2_rn(v2, v3));
        }
    }
    __syncwarp();

    float acc3[2][4];
#pragma unroll
    for (int i = 0; i < 2; i++)
#pragma unroll
        for (int q = 0; q < 4; q++) acc3[i][q] = 0.f;
#pragma unroll
    for (int ks = 0; ks < 2; ks++) {
        uint32_t a[2][4];
#pragma unroll
        for (int ma = 0; ma < 2; ma++) {
            int row = w * 32 + ma * 16 + lq;
            uint32_t o = OFF_H2 + row * (MLP_LDH * 2) + (ks * 16 + lr * 2) * 2;
            a[ma][0] = *reinterpret_cast<uint32_t*>(sm + o);
            a[ma][1] = *reinterpret_cast<uint32_t*>(sm + o + 8 * (MLP_LDH * 2));
            a[ma][2] = *reinterpret_cast<uint32_t*>(sm + o + 16);
            a[ma][3] = *reinterpret_cast<uint32_t*>(sm + o + 8 * (MLP_LDH * 2) + 16);
        }
        int n = lq;
        uint32_t o = OFF_W3 + n * (MLP_LDH * 2) + (ks * 16 + lr * 2) * 2;
        uint32_t b[2];
        b[0] = *reinterpret_cast<uint32_t*>(sm + o);
        b[1] = *reinterpret_cast<uint32_t*>(sm + o + 16);
#pragma unroll
        for (int ma = 0; ma < 2; ma++) mma16816ha(acc3[ma], a[ma], b);
    }
    if (lr < 2) {
        int ca = 2 * lr, cb = 2 * lr + 1;
#pragma unroll
        for (int ma = 0; ma < 2; ma++) {
            int r0 = bm + w * 32 + ma * 16 + lq;
            int r1 = r0 + 8;
            if (r0 < N_NODES) {
                float s0 = softplus_f(acc3[ma][0] + fb3[ca]);
                float s1 = softplus_f(acc3[ma][1] + fb3[cb]);
                if (ca == 0) out[r0] = s0; else out[N_NODES + (size_t)r0 * 3 + ca - 1] = s0;
                out[N_NODES + (size_t)r0 * 3 + cb - 1] = s1;
            }
            if (r1 < N_NODES) {
                float s2 = softplus_f(acc3[ma][2] + fb3[ca]);
                float s3 = softplus_f(acc3[ma][3] + fb3[cb]);
                if (ca == 0) out[r1] = s2; else out[N_NODES + (size_t)r1 * 3 + ca - 1] = s2;
                out[N_NODES + (size_t)r1 * 3 + cb - 1] = s3;
            }
        }
    }
}

// ---------------------------------------------------------------- launch
extern "C" void kernel_launch(void* const* d_in, const int* in_sizes, int n_in,
                              void* d_out, int out_size)
{
    const float* x    = (const float*)d_in[0];
    const int*   ei   = (const int*)  d_in[1];
    const float* aW   = (const float*)d_in[2];
    const float* ab   = (const float*)d_in[3];
    const float* aW1  = (const float*)d_in[4];
    const float* ab1  = (const float*)d_in[5];
    const float* aW2  = (const float*)d_in[6];
    const float* ab2  = (const float*)d_in[7];
    const float* aW3  = (const float*)d_in[8];
    const float* ab3  = (const float*)d_in[9];
    const float* cW   = (const float*)d_in[10];
    const float* cb   = (const float*)d_in[11];
    const float* cW1  = (const float*)d_in[12];
    const float* cb1  = (const float*)d_in[13];
    const float* cW2  = (const float*)d_in[14];
    const float* cb2  = (const float*)d_in[15];
    const float* cW3  = (const float*)d_in[16];
    const float* cb3  = (const float*)d_in[17];
    float* out = (float*)d_out;

    const int* src = ei;
    const int* dst = ei + N_EDGES;

    cudaFuncSetAttribute((const void*)k_gemm_fill,
                         cudaFuncAttributeMaxDynamicSharedMemorySize, SM_TOTAL_MMA);
    cudaFuncSetAttribute((const void*)k_mlp,
                         cudaFuncAttributeMaxDynamicSharedMemorySize, MLP_SMEM);

    k_degree_prep<<<FILL_B + WPREP_B + MLPP_B, 256>>>(dst, aW, cW, aW1, aW2, aW3);
    k_scan1      <<<SCAN_G, SCAN_B>>>();
    k_scan3      <<<SCAN_G, SCAN_B>>>();

    k_gemm_fill<<<2 * GEMM_BX + FILL_B, 256, SM_TOTAL_MMA>>>(x, src, dst);

    k_aggregate<<<2048, 256>>>(x, ab, cb);

    k_mlp<<<GEMM_BX + 1, 128, MLP_SMEM>>>(ab1, ab2, ab3,
                                          cW1, cb1, cW2, cb2, cW3, cb3, out);
}